// round 7
// baseline (speedup 1.0000x reference)
#include <cuda_runtime.h>
#include <stdint.h>
#include <math.h>

// ---------------- problem constants ----------------
#define CDIM   1024
#define NTOK   16384             // B*T = 4*4096
#define C3     (3 * CDIM)        // 3072

// ---------------- scratch (allocation-free rule) ----------------
__device__ float g_qkv[(size_t)NTOK * C3];
__device__ float g_y  [(size_t)NTOK * CDIM];

// ---------------- PTX helpers (baseline sm_80+ only) ----------------
__device__ __forceinline__ uint32_t smem_u32(const void* p) {
    uint32_t a;
    asm("{ .reg .u64 t; cvta.to.shared.u64 t, %1; cvt.u32.u64 %0, t; }"
        : "=r"(a) : "l"(p));
    return a;
}

#define CP_ASYNC16(dst_u32, src_ptr) \
    asm volatile("cp.async.cg.shared.global [%0], [%1], 16;" \
                 :: "r"(dst_u32), "l"(src_ptr) : "memory")
#define CP_COMMIT() asm volatile("cp.async.commit_group;" ::: "memory")
#define CP_WAIT(n)  asm volatile("cp.async.wait_group %0;" :: "n"(n) : "memory")

#define LDSM4(r, addr) \
    asm volatile("ldmatrix.sync.aligned.m8n8.x4.shared.b16 {%0,%1,%2,%3}, [%4];" \
        : "=r"((r)[0]), "=r"((r)[1]), "=r"((r)[2]), "=r"((r)[3]) : "r"(addr))

#define MMA_TF32(d, a, b0, b1) \
    asm volatile("mma.sync.aligned.m16n8k8.row.col.f32.tf32.tf32.f32 " \
        "{%0,%1,%2,%3}, {%4,%5,%6,%7}, {%8,%9}, {%0,%1,%2,%3};" \
        : "+f"((d)[0]), "+f"((d)[1]), "+f"((d)[2]), "+f"((d)[3]) \
        : "r"((a)[0]), "r"((a)[1]), "r"((a)[2]), "r"((a)[3]), "r"(b0), "r"(b1))

__device__ __forceinline__ uint32_t f2tf32(float x) {
    uint32_t r;
    asm("cvt.rna.tf32.f32 %0, %1;" : "=r"(r) : "f"(x));
    return r;
}
// round a 32-bit fragment register (fp32 bits) to tf32 in place
__device__ __forceinline__ void rnd4(uint32_t* r) {
    #pragma unroll
    for (int q = 0; q < 4; q++)
        asm("cvt.rna.tf32.f32 %0, %0;" : "+r"(r[q]));
}

// ---------------- smem geometry (XOR swizzle, pitch = 128 B exact) ----------------
#define PITCH   128
#define TILE_B  (128 * PITCH)      // 16384 B
#define OFF_B   TILE_B
#define STAGE_B (2 * TILE_B)       // 32768 B
#define NSTG    3
#define SMEM_B  (NSTG * STAGE_B)   // 98304 B -> 2 CTAs/SM
#define BKC     32                 // K per chunk (4 k8 steps)

// ---------------------------------------------------------------------------
// C[M,N] = A[M,K] @ B[N,K]^T (+bias); raw fp32 inputs, tf32 rounding applied
// in-register on fragments (cvt.rna). 128x128 CTA tile, 8 warps (64x32 each),
// 3-stage cp.async, TF32 HMMA, 2 CTAs/SM, warp-rotated k-step order.
// ---------------------------------------------------------------------------
__global__ __launch_bounds__(256, 2) void tf32_gemm(
    const float* __restrict__ A, const float* __restrict__ B,
    const float* __restrict__ bias, float* __restrict__ C,
    int M, int N, int K)
{
    extern __shared__ char sm[];
    const uint32_t sbase = smem_u32(sm);

    const int tid  = threadIdx.x;
    const int lane = tid & 31;
    const int wid  = tid >> 5;
    const int wm   = wid & 1;       // M half
    const int wn   = wid >> 1;      // N quarter
    const int bm   = blockIdx.y * 128;
    const int bn   = blockIdx.x * 128;

    // ---- loader mapping: 128 rows x 2 half-rows(64 B) ----
    const int lr = tid >> 1;
    const int lh = tid & 1;
    const float* gA = A + (size_t)(bm + lr) * K + lh * 16;
    const float* gB = B + (size_t)(bn + lr) * K + lh * 16;
    uint32_t sw[4];
    #pragma unroll
    for (int j = 0; j < 4; j++) sw[j] = (uint32_t)(((lh * 4 + j) ^ (lr & 7)) << 4);
    const uint32_t sRowBase = (uint32_t)(lr * PITCH);

    // ---- ldmatrix lane addressing (row&7 == lane&7 within each 8-row tile) ----
    const int g  = lane >> 3;
    const int l8 = lane & 7;
    const int cA = g >> 1;
    const int cB = g & 1;
    const uint32_t aRow = (uint32_t)((wm * 64 + l8 + (g & 1) * 8) * PITCH);
    const uint32_t bRow = (uint32_t)((wn * 32 + l8 + (g >> 1) * 8) * PITCH);
    uint32_t aSw[4], bSw[4];
    #pragma unroll
    for (int s = 0; s < 4; s++) {
        aSw[s] = (uint32_t)(((s * 2 + cA) ^ l8) << 4);
        bSw[s] = (uint32_t)(((s * 2 + cB) ^ l8) << 4);
    }

    float acc[4][4][4];
    #pragma unroll
    for (int i = 0; i < 4; i++)
        #pragma unroll
        for (int j = 0; j < 4; j++)
            #pragma unroll
            for (int q = 0; q < 4; q++) acc[i][j][q] = 0.0f;

    const int KC = K / BKC;
    const int s0 = wid & 3;          // per-warp k-step rotation (de-convoy)

    auto issue = [&](int stg, int ko) {
        const uint32_t dA = sbase + (uint32_t)stg * STAGE_B + sRowBase;
        const uint32_t dB = dA + OFF_B;
        const float* sa = gA + ko;
        const float* sb = gB + ko;
        #pragma unroll
        for (int j = 0; j < 4; j++) {
            CP_ASYNC16(dA + sw[j], sa + j * 4);
            CP_ASYNC16(dB + sw[j], sb + j * 4);
        }
    };

    // frag load for one k8 step (with in-register tf32 rounding)
    uint32_t af[2][4][4], bf[2][2][4];
    auto ldfrag = [&](int buf, int s, uint32_t aB, uint32_t bB) {
        #pragma unroll
        for (int i = 0; i < 4; i++) {
            LDSM4(af[buf][i], aB + aSw[s] + (uint32_t)(i * 16 * PITCH));
            rnd4(af[buf][i]);
        }
        #pragma unroll
        for (int p = 0; p < 2; p++) {
            LDSM4(bf[buf][p], bB + bSw[s] + (uint32_t)(p * 16 * PITCH));
            rnd4(bf[buf][p]);
        }
    };

    // prologue: 2 stages in flight
    issue(0, 0);   CP_COMMIT();
    issue(1, BKC); CP_COMMIT();

    for (int c = 0; c < KC; c++) {
        if (c == KC - 1) { CP_WAIT(0); } else { CP_WAIT(1); }
        __syncthreads();
        if (c + 2 < KC) { issue((c + 2) % NSTG, (c + 2) * BKC); CP_COMMIT(); }

        const uint32_t stg = sbase + (uint32_t)(c % NSTG) * STAGE_B;
        const uint32_t aB  = stg + aRow;
        const uint32_t bB  = stg + OFF_B + bRow;

        ldfrag(0, s0, aB, bB);

        #pragma unroll
        for (int ss = 0; ss < 4; ss++) {
            const int cur = ss & 1;
            if (ss < 3) ldfrag(cur ^ 1, (s0 + ss + 1) & 3, aB, bB);
            #pragma unroll
            for (int i = 0; i < 4; i++) {
                #pragma unroll
                for (int j = 0; j < 4; j++) {
                    const int p = j >> 1, q = j & 1;
                    MMA_TF32(acc[i][j], af[cur][i], bf[cur][p][q * 2], bf[cur][p][q * 2 + 1]);
                }
            }
        }
    }

    // ---- epilogue ----
    #pragma unroll
    for (int i = 0; i < 4; i++) {
        const int row = bm + wm * 64 + i * 16 + (lane >> 2);
        #pragma unroll
        for (int j = 0; j < 4; j++) {
            const int col = bn + wn * 32 + j * 8 + (lane & 3) * 2;
            float b0 = 0.f, b1 = 0.f;
            if (bias) { b0 = bias[col]; b1 = bias[col + 1]; }
            float2 v0 = make_float2(acc[i][j][0] + b0, acc[i][j][1] + b1);
            float2 v1 = make_float2(acc[i][j][2] + b0, acc[i][j][3] + b1);
            *(float2*)(C + (size_t)row * N + col)       = v0;
            *(float2*)(C + (size_t)(row + 8) * N + col) = v1;
        }
    }
}

// ---------------------------------------------------------------------------
// Per-token attention over heads (fp32); plain fp32 output (GEMM2 rounds).
// ---------------------------------------------------------------------------
__global__ __launch_bounds__(256) void attn_kernel(
    const float* __restrict__ qkv, float* __restrict__ y)
{
    __shared__ float sh[C3];
    __shared__ float att[16][16];

    const int token = blockIdx.x;
    const int tid   = threadIdx.x;
    const float* row = qkv + (size_t)token * C3;

    for (int i = tid; i < C3 / 4; i += 256)
        ((float4*)sh)[i] = ((const float4*)row)[i];
    __syncthreads();

    const int h = tid >> 4;
    const int gg = tid & 15;
    const float* qp = sh + h * 192;
    const float* kp = sh + gg * 192 + 64;

    float s = 0.0f;
    #pragma unroll
    for (int dd = 0; dd < 64; dd++) {
        int d = (dd + gg) & 63;
        s += qp[d] * kp[d];
    }
    att[h][gg] = s * 0.125f;
    __syncthreads();

    float m = -1e30f;
    #pragma unroll
    for (int j = 0; j < 16; j++) m = fmaxf(m, att[h][j]);
    float e = __expf(att[h][gg] - m);
    __syncthreads();
    att[h][gg] = e;
    __syncthreads();
    float denom = 0.0f;
    #pragma unroll
    for (int j = 0; j < 16; j++) denom += att[h][j];
    const float inv = 1.0f / denom;

    const int d0 = (tid & 15) * 4;
    float4 o = make_float4(0.f, 0.f, 0.f, 0.f);
    #pragma unroll
    for (int g2 = 0; g2 < 16; g2++) {
        const float w = att[h][g2];
        const float* vp = sh + g2 * 192 + 128 + d0;
        o.x += w * vp[0];
        o.y += w * vp[1];
        o.z += w * vp[2];
        o.w += w * vp[3];
    }
    o.x *= inv; o.y *= inv; o.z *= inv; o.w *= inv;
    *(float4*)(y + (size_t)token * CDIM + h * 64 + d0) = o;
}

// ---------------------------------------------------------------------------
extern "C" void kernel_launch(void* const* d_in, const int* in_sizes, int n_in,
                              void* d_out, int out_size)
{
    const float* x    = (const float*)d_in[0];
    const float* Wqkv = (const float*)d_in[1];
    const float* Wout = (const float*)d_in[2];
    const float* bout = (const float*)d_in[3];
    float* out = (float*)d_out;

    float *qkv, *y;
    cudaGetSymbolAddress((void**)&qkv, g_qkv);
    cudaGetSymbolAddress((void**)&y,   g_y);

    cudaFuncSetAttribute(tf32_gemm, cudaFuncAttributeMaxDynamicSharedMemorySize, SMEM_B);

    // GEMM1: qkv = x @ Wqkv^T   (16384 x 3072, K=1024) — tf32 rounding in-kernel
    tf32_gemm<<<dim3(C3 / 128, NTOK / 128), 256, SMEM_B>>>(
        x, Wqkv, nullptr, qkv, NTOK, C3, CDIM);

    // attention over heads
    attn_kernel<<<NTOK, 256>>>(qkv, y);

    // GEMM2: out = y @ Wout^T + bout   (16384 x 1024, K=1024)
    tf32_gemm<<<dim3(CDIM / 128, NTOK / 128), 256, SMEM_B>>>(
        y, Wout, bout, out, NTOK, CDIM, CDIM);
}

// round 8
// speedup vs baseline: 1.1487x; 1.1487x over previous
#include <cuda_runtime.h>
#include <stdint.h>
#include <math.h>

// ---------------- problem constants ----------------
#define CDIM   1024
#define NTOK   16384             // B*T = 4*4096
#define C3     (3 * CDIM)        // 3072

// ---------------- scratch (allocation-free rule) ----------------
__device__ float g_qkv[(size_t)NTOK * C3];
__device__ float g_y  [(size_t)NTOK * CDIM];
__device__ float g_xt [(size_t)NTOK * CDIM];
__device__ float g_w1t[(size_t)C3 * CDIM];
__device__ float g_w2t[(size_t)CDIM * CDIM];

// ---------------- PTX helpers (baseline sm_80+ only) ----------------
__device__ __forceinline__ uint32_t smem_u32(const void* p) {
    uint32_t a;
    asm("{ .reg .u64 t; cvta.to.shared.u64 t, %1; cvt.u32.u64 %0, t; }"
        : "=r"(a) : "l"(p));
    return a;
}

#define CP_ASYNC16(dst_u32, src_ptr) \
    asm volatile("cp.async.cg.shared.global [%0], [%1], 16;" \
                 :: "r"(dst_u32), "l"(src_ptr) : "memory")
#define CP_COMMIT() asm volatile("cp.async.commit_group;" ::: "memory")
#define CP_WAIT(n)  asm volatile("cp.async.wait_group %0;" :: "n"(n) : "memory")

#define LDSM4(r, addr) \
    asm volatile("ldmatrix.sync.aligned.m8n8.x4.shared.b16 {%0,%1,%2,%3}, [%4];" \
        : "=r"((r)[0]), "=r"((r)[1]), "=r"((r)[2]), "=r"((r)[3]) : "r"(addr))

#define MMA_TF32(d, a, b0, b1) \
    asm volatile("mma.sync.aligned.m16n8k8.row.col.f32.tf32.tf32.f32 " \
        "{%0,%1,%2,%3}, {%4,%5,%6,%7}, {%8,%9}, {%0,%1,%2,%3};" \
        : "+f"((d)[0]), "+f"((d)[1]), "+f"((d)[2]), "+f"((d)[3]) \
        : "r"((a)[0]), "r"((a)[1]), "r"((a)[2]), "r"((a)[3]), "r"(b0), "r"(b1))

__device__ __forceinline__ uint32_t f2tf32(float x) {
    uint32_t r;
    asm("cvt.rna.tf32.f32 %0, %1;" : "=r"(r) : "f"(x));
    return r;
}

// ---------------- smem geometry (XOR swizzle, pitch = 128 B exact) ----------------
#define PITCH   128
#define TILE_B  (128 * PITCH)      // 16384 B
#define OFF_B   TILE_B
#define STAGE_B (2 * TILE_B)       // 32768 B
#define NSTG    3
#define SMEM_B  (NSTG * STAGE_B)   // 98304 B -> 2 CTAs/SM
#define BKC     32                 // K per chunk (4 k8 steps)

// ---------------------------------------------------------------------------
// C[M,N] = A[M,K] @ B[N,K]^T (+bias); A,B fp32 already tf32-rounded.
// 128x128 CTA tile, 8 warps (64x32 each), 3-stage cp.async, TF32 HMMA,
// 2 CTAs/SM. LDSM hand-interleaved into the MMA stream (both volatile ->
// source order preserved -> port and tensor pipe overlap instead of
// alternating in convoy).
// ---------------------------------------------------------------------------
__global__ __launch_bounds__(256, 2) void tf32_gemm(
    const float* __restrict__ A, const float* __restrict__ B,
    const float* __restrict__ bias, float* __restrict__ C,
    int M, int N, int K)
{
    extern __shared__ char sm[];
    const uint32_t sbase = smem_u32(sm);

    const int tid  = threadIdx.x;
    const int lane = tid & 31;
    const int wid  = tid >> 5;
    const int wm   = wid & 1;       // M half
    const int wn   = wid >> 1;      // N quarter
    const int bm   = blockIdx.y * 128;
    const int bn   = blockIdx.x * 128;

    // ---- loader mapping: 128 rows x 2 half-rows(64 B) ----
    const int lr = tid >> 1;
    const int lh = tid & 1;
    const float* gA = A + (size_t)(bm + lr) * K + lh * 16;
    const float* gB = B + (size_t)(bn + lr) * K + lh * 16;
    uint32_t sw[4];
    #pragma unroll
    for (int j = 0; j < 4; j++) sw[j] = (uint32_t)(((lh * 4 + j) ^ (lr & 7)) << 4);
    const uint32_t sRowBase = (uint32_t)(lr * PITCH);

    // ---- ldmatrix lane addressing (row&7 == lane&7 within each 8-row tile) ----
    const int g  = lane >> 3;
    const int l8 = lane & 7;
    const int cA = g >> 1;
    const int cB = g & 1;
    const uint32_t aRow = (uint32_t)((wm * 64 + l8 + (g & 1) * 8) * PITCH);
    const uint32_t bRow = (uint32_t)((wn * 32 + l8 + (g >> 1) * 8) * PITCH);
    uint32_t aSw[4], bSw[4];
    #pragma unroll
    for (int s = 0; s < 4; s++) {
        aSw[s] = (uint32_t)(((s * 2 + cA) ^ l8) << 4);
        bSw[s] = (uint32_t)(((s * 2 + cB) ^ l8) << 4);
    }

    float acc[4][4][4];
    #pragma unroll
    for (int i = 0; i < 4; i++)
        #pragma unroll
        for (int j = 0; j < 4; j++)
            #pragma unroll
            for (int q = 0; q < 4; q++) acc[i][j][q] = 0.0f;

    const int KC = K / BKC;

    auto issue = [&](int stg, int ko) {
        const uint32_t dA = sbase + (uint32_t)stg * STAGE_B + sRowBase;
        const uint32_t dB = dA + OFF_B;
        const float* sa = gA + ko;
        const float* sb = gB + ko;
        #pragma unroll
        for (int j = 0; j < 4; j++) {
            CP_ASYNC16(dA + sw[j], sa + j * 4);
            CP_ASYNC16(dB + sw[j], sb + j * 4);
        }
    };

    // prologue: 2 stages in flight
    issue(0, 0);   CP_COMMIT();
    issue(1, BKC); CP_COMMIT();

    uint32_t af[2][4][4], bf[2][2][4];

    for (int c = 0; c < KC; c++) {
        if (c == KC - 1) { CP_WAIT(0); } else { CP_WAIT(1); }
        __syncthreads();
        if (c + 2 < KC) { issue((c + 2) % NSTG, (c + 2) * BKC); CP_COMMIT(); }

        const uint32_t stg = sbase + (uint32_t)(c % NSTG) * STAGE_B;
        const uint32_t aB  = stg + aRow;
        const uint32_t bB  = stg + OFF_B + bRow;

        // frags for k8-step 0
        #pragma unroll
        for (int i = 0; i < 4; i++) LDSM4(af[0][i], aB + aSw[0] + (uint32_t)(i * 16 * PITCH));
        #pragma unroll
        for (int p = 0; p < 2; p++) LDSM4(bf[0][p], bB + bSw[0] + (uint32_t)(p * 16 * PITCH));

        #pragma unroll
        for (int s = 0; s < 4; s++) {
            const int cur = s & 1;
            const int nxt = cur ^ 1;
            // 16 MMAs for step s, with next step's 6 LDSMs woven in
            #pragma unroll
            for (int m = 0; m < 16; m++) {
                const int i = m >> 2, j = m & 3;
                const int p = j >> 1, q = j & 1;
                MMA_TF32(acc[i][j], af[cur][i], bf[cur][p][q * 2], bf[cur][p][q * 2 + 1]);
                if (s < 3) {
                    if (m == 2)
                        LDSM4(af[nxt][0], aB + aSw[s + 1] + (uint32_t)(0 * 16 * PITCH));
                    if (m == 4)
                        LDSM4(af[nxt][1], aB + aSw[s + 1] + (uint32_t)(1 * 16 * PITCH));
                    if (m == 6)
                        LDSM4(af[nxt][2], aB + aSw[s + 1] + (uint32_t)(2 * 16 * PITCH));
                    if (m == 8)
                        LDSM4(af[nxt][3], aB + aSw[s + 1] + (uint32_t)(3 * 16 * PITCH));
                    if (m == 10)
                        LDSM4(bf[nxt][0], bB + bSw[s + 1] + (uint32_t)(0 * 16 * PITCH));
                    if (m == 12)
                        LDSM4(bf[nxt][1], bB + bSw[s + 1] + (uint32_t)(1 * 16 * PITCH));
                }
            }
        }
    }

    // ---- epilogue ----
    #pragma unroll
    for (int i = 0; i < 4; i++) {
        const int row = bm + wm * 64 + i * 16 + (lane >> 2);
        #pragma unroll
        for (int j = 0; j < 4; j++) {
            const int col = bn + wn * 32 + j * 8 + (lane & 3) * 2;
            float b0 = 0.f, b1 = 0.f;
            if (bias) { b0 = bias[col]; b1 = bias[col + 1]; }
            float2 v0 = make_float2(acc[i][j][0] + b0, acc[i][j][1] + b1);
            float2 v1 = make_float2(acc[i][j][2] + b0, acc[i][j][3] + b1);
            *(float2*)(C + (size_t)row * N + col)       = v0;
            *(float2*)(C + (size_t)(row + 8) * N + col) = v1;
        }
    }
}

// ---------------------------------------------------------------------------
// fp32 -> tf32-rounded fp32 (cvt.rna)
// ---------------------------------------------------------------------------
__global__ __launch_bounds__(256) void round_tf32_kernel(
    const float* __restrict__ src, float* __restrict__ dst, int n4)
{
    const int i = blockIdx.x * blockDim.x + threadIdx.x;
    if (i >= n4) return;
    const float4 v = ((const float4*)src)[i];
    uint4 r;
    r.x = f2tf32(v.x); r.y = f2tf32(v.y);
    r.z = f2tf32(v.z); r.w = f2tf32(v.w);
    ((uint4*)dst)[i] = r;
}

// ---------------------------------------------------------------------------
// Per-token attention over heads (fp32), outputs tf32-rounded y.
// ---------------------------------------------------------------------------
__global__ __launch_bounds__(256) void attn_kernel(
    const float* __restrict__ qkv, float* __restrict__ y)
{
    __shared__ float sh[C3];
    __shared__ float att[16][16];

    const int token = blockIdx.x;
    const int tid   = threadIdx.x;
    const float* row = qkv + (size_t)token * C3;

    for (int i = tid; i < C3 / 4; i += 256)
        ((float4*)sh)[i] = ((const float4*)row)[i];
    __syncthreads();

    const int h = tid >> 4;
    const int gg = tid & 15;
    const float* qp = sh + h * 192;
    const float* kp = sh + gg * 192 + 64;

    float s = 0.0f;
    #pragma unroll
    for (int dd = 0; dd < 64; dd++) {
        int d = (dd + gg) & 63;
        s += qp[d] * kp[d];
    }
    att[h][gg] = s * 0.125f;
    __syncthreads();

    float m = -1e30f;
    #pragma unroll
    for (int j = 0; j < 16; j++) m = fmaxf(m, att[h][j]);
    float e = __expf(att[h][gg] - m);
    __syncthreads();
    att[h][gg] = e;
    __syncthreads();
    float denom = 0.0f;
    #pragma unroll
    for (int j = 0; j < 16; j++) denom += att[h][j];
    const float inv = 1.0f / denom;

    const int d0 = (tid & 15) * 4;
    float4 o = make_float4(0.f, 0.f, 0.f, 0.f);
    #pragma unroll
    for (int g2 = 0; g2 < 16; g2++) {
        const float w = att[h][g2];
        const float* vp = sh + g2 * 192 + 128 + d0;
        o.x += w * vp[0];
        o.y += w * vp[1];
        o.z += w * vp[2];
        o.w += w * vp[3];
    }
    uint4 r;
    r.x = f2tf32(o.x * inv);
    r.y = f2tf32(o.y * inv);
    r.z = f2tf32(o.z * inv);
    r.w = f2tf32(o.w * inv);
    *(uint4*)(y + (size_t)token * CDIM + h * 64 + d0) = r;
}

// ---------------------------------------------------------------------------
extern "C" void kernel_launch(void* const* d_in, const int* in_sizes, int n_in,
                              void* d_out, int out_size)
{
    const float* x    = (const float*)d_in[0];
    const float* Wqkv = (const float*)d_in[1];
    const float* Wout = (const float*)d_in[2];
    const float* bout = (const float*)d_in[3];
    float* out = (float*)d_out;

    float *qkv, *y, *xt, *w1t, *w2t;
    cudaGetSymbolAddress((void**)&qkv, g_qkv);
    cudaGetSymbolAddress((void**)&y,   g_y);
    cudaGetSymbolAddress((void**)&xt,  g_xt);
    cudaGetSymbolAddress((void**)&w1t, g_w1t);
    cudaGetSymbolAddress((void**)&w2t, g_w2t);

    cudaFuncSetAttribute(tf32_gemm, cudaFuncAttributeMaxDynamicSharedMemorySize, SMEM_B);

    // tf32 rounding passes (rna)
    round_tf32_kernel<<<(NTOK * CDIM / 4 + 255) / 256, 256>>>(x, xt, NTOK * CDIM / 4);
    round_tf32_kernel<<<(C3 * CDIM / 4 + 255) / 256, 256>>>(Wqkv, w1t, C3 * CDIM / 4);
    round_tf32_kernel<<<(CDIM * CDIM / 4 + 255) / 256, 256>>>(Wout, w2t, CDIM * CDIM / 4);

    // GEMM1: qkv = xt @ w1t^T   (16384 x 3072, K=1024)
    tf32_gemm<<<dim3(C3 / 128, NTOK / 128), 256, SMEM_B>>>(
        xt, w1t, nullptr, qkv, NTOK, C3, CDIM);

    // attention over heads (emits tf32-rounded y)
    attn_kernel<<<NTOK, 256>>>(qkv, y);

    // GEMM2: out = y @ w2t^T + bout   (16384 x 1024, K=1024)
    tf32_gemm<<<dim3(CDIM / 128, NTOK / 128), 256, SMEM_B>>>(
        y, w2t, bout, out, NTOK, CDIM, CDIM);
}

// round 10
// speedup vs baseline: 1.1959x; 1.0410x over previous
#include <cuda_runtime.h>
#include <stdint.h>
#include <math.h>

// ---------------- problem constants ----------------
#define CDIM   1024
#define NTOK   16384             // B*T = 4*4096
#define C3     (3 * CDIM)        // 3072

// ---------------- scratch (allocation-free rule) ----------------
__device__ float g_qkv[(size_t)NTOK * C3];
__device__ float g_y  [(size_t)NTOK * CDIM];
__device__ float g_xt [(size_t)NTOK * CDIM];
__device__ float g_w1t[(size_t)C3 * CDIM];
__device__ float g_w2t[(size_t)CDIM * CDIM];

// ---------------- PTX helpers (baseline sm_80+ only) ----------------
__device__ __forceinline__ uint32_t smem_u32(const void* p) {
    uint32_t a;
    asm("{ .reg .u64 t; cvta.to.shared.u64 t, %1; cvt.u32.u64 %0, t; }"
        : "=r"(a) : "l"(p));
    return a;
}

#define CP_ASYNC16(dst_u32, src_ptr) \
    asm volatile("cp.async.cg.shared.global [%0], [%1], 16;" \
                 :: "r"(dst_u32), "l"(src_ptr) : "memory")
#define CP_COMMIT() asm volatile("cp.async.commit_group;" ::: "memory")
#define CP_WAIT(n)  asm volatile("cp.async.wait_group %0;" :: "n"(n) : "memory")

#define LDSM4(r, addr) \
    asm volatile("ldmatrix.sync.aligned.m8n8.x4.shared.b16 {%0,%1,%2,%3}, [%4];" \
        : "=r"((r)[0]), "=r"((r)[1]), "=r"((r)[2]), "=r"((r)[3]) : "r"(addr))

#define MMA_TF32(d, a, b0, b1) \
    asm volatile("mma.sync.aligned.m16n8k8.row.col.f32.tf32.tf32.f32 " \
        "{%0,%1,%2,%3}, {%4,%5,%6,%7}, {%8,%9}, {%0,%1,%2,%3};" \
        : "+f"((d)[0]), "+f"((d)[1]), "+f"((d)[2]), "+f"((d)[3]) \
        : "r"((a)[0]), "r"((a)[1]), "r"((a)[2]), "r"((a)[3]), "r"(b0), "r"(b1))

__device__ __forceinline__ uint32_t f2tf32(float x) {
    uint32_t r;
    asm("cvt.rna.tf32.f32 %0, %1;" : "=r"(r) : "f"(x));
    return r;
}

// ---------------- GEMM smem geometry (XOR swizzle, pitch = 128 B exact) ----------------
#define PITCH   128
#define TILE_B  (128 * PITCH)      // 16384 B
#define OFF_B   TILE_B
#define STAGE_B (2 * TILE_B)       // 32768 B
#define NSTG    3
#define SMEM_B  (NSTG * STAGE_B)   // 98304 B -> 2 CTAs/SM
#define BKC     32                 // K per chunk (4 k8 steps)

// ---------------------------------------------------------------------------
// GEMM — identical to round 8 (at the tf32-MMA instruction floor).
// ---------------------------------------------------------------------------
__global__ __launch_bounds__(256, 2) void tf32_gemm(
    const float* __restrict__ A, const float* __restrict__ B,
    const float* __restrict__ bias, float* __restrict__ C,
    int M, int N, int K)
{
    extern __shared__ char sm[];
    const uint32_t sbase = smem_u32(sm);

    const int tid  = threadIdx.x;
    const int lane = tid & 31;
    const int wid  = tid >> 5;
    const int wm   = wid & 1;
    const int wn   = wid >> 1;
    const int bm   = blockIdx.y * 128;
    const int bn   = blockIdx.x * 128;

    const int lr = tid >> 1;
    const int lh = tid & 1;
    const float* gA = A + (size_t)(bm + lr) * K + lh * 16;
    const float* gB = B + (size_t)(bn + lr) * K + lh * 16;
    uint32_t sw[4];
    #pragma unroll
    for (int j = 0; j < 4; j++) sw[j] = (uint32_t)(((lh * 4 + j) ^ (lr & 7)) << 4);
    const uint32_t sRowBase = (uint32_t)(lr * PITCH);

    const int g  = lane >> 3;
    const int l8 = lane & 7;
    const int cA = g >> 1;
    const int cB = g & 1;
    const uint32_t aRow = (uint32_t)((wm * 64 + l8 + (g & 1) * 8) * PITCH);
    const uint32_t bRow = (uint32_t)((wn * 32 + l8 + (g >> 1) * 8) * PITCH);
    uint32_t aSw[4], bSw[4];
    #pragma unroll
    for (int s = 0; s < 4; s++) {
        aSw[s] = (uint32_t)(((s * 2 + cA) ^ l8) << 4);
        bSw[s] = (uint32_t)(((s * 2 + cB) ^ l8) << 4);
    }

    float acc[4][4][4];
    #pragma unroll
    for (int i = 0; i < 4; i++)
        #pragma unroll
        for (int j = 0; j < 4; j++)
            #pragma unroll
            for (int q = 0; q < 4; q++) acc[i][j][q] = 0.0f;

    const int KC = K / BKC;

    auto issue = [&](int stg, int ko) {
        const uint32_t dA = sbase + (uint32_t)stg * STAGE_B + sRowBase;
        const uint32_t dB = dA + OFF_B;
        const float* sa = gA + ko;
        const float* sb = gB + ko;
        #pragma unroll
        for (int j = 0; j < 4; j++) {
            CP_ASYNC16(dA + sw[j], sa + j * 4);
            CP_ASYNC16(dB + sw[j], sb + j * 4);
        }
    };

    issue(0, 0);   CP_COMMIT();
    issue(1, BKC); CP_COMMIT();

    uint32_t af[2][4][4], bf[2][2][4];

    for (int c = 0; c < KC; c++) {
        if (c == KC - 1) { CP_WAIT(0); } else { CP_WAIT(1); }
        __syncthreads();
        if (c + 2 < KC) { issue((c + 2) % NSTG, (c + 2) * BKC); CP_COMMIT(); }

        const uint32_t stg = sbase + (uint32_t)(c % NSTG) * STAGE_B;
        const uint32_t aB  = stg + aRow;
        const uint32_t bB  = stg + OFF_B + bRow;

        #pragma unroll
        for (int i = 0; i < 4; i++) LDSM4(af[0][i], aB + aSw[0] + (uint32_t)(i * 16 * PITCH));
        #pragma unroll
        for (int p = 0; p < 2; p++) LDSM4(bf[0][p], bB + bSw[0] + (uint32_t)(p * 16 * PITCH));

        #pragma unroll
        for (int s = 0; s < 4; s++) {
            const int cur = s & 1;
            const int nxt = cur ^ 1;
            #pragma unroll
            for (int m = 0; m < 16; m++) {
                const int i = m >> 2, j = m & 3;
                const int p = j >> 1, q = j & 1;
                MMA_TF32(acc[i][j], af[cur][i], bf[cur][p][q * 2], bf[cur][p][q * 2 + 1]);
                if (s < 3) {
                    if (m == 2)
                        LDSM4(af[nxt][0], aB + aSw[s + 1] + (uint32_t)(0 * 16 * PITCH));
                    if (m == 4)
                        LDSM4(af[nxt][1], aB + aSw[s + 1] + (uint32_t)(1 * 16 * PITCH));
                    if (m == 6)
                        LDSM4(af[nxt][2], aB + aSw[s + 1] + (uint32_t)(2 * 16 * PITCH));
                    if (m == 8)
                        LDSM4(af[nxt][3], aB + aSw[s + 1] + (uint32_t)(3 * 16 * PITCH));
                    if (m == 10)
                        LDSM4(bf[nxt][0], bB + bSw[s + 1] + (uint32_t)(0 * 16 * PITCH));
                    if (m == 12)
                        LDSM4(bf[nxt][1], bB + bSw[s + 1] + (uint32_t)(1 * 16 * PITCH));
                }
            }
        }
    }

    #pragma unroll
    for (int i = 0; i < 4; i++) {
        const int row = bm + wm * 64 + i * 16 + (lane >> 2);
        #pragma unroll
        for (int j = 0; j < 4; j++) {
            const int col = bn + wn * 32 + j * 8 + (lane & 3) * 2;
            float b0 = 0.f, b1 = 0.f;
            if (bias) { b0 = bias[col]; b1 = bias[col + 1]; }
            float2 v0 = make_float2(acc[i][j][0] + b0, acc[i][j][1] + b1);
            float2 v1 = make_float2(acc[i][j][2] + b0, acc[i][j][3] + b1);
            *(float2*)(C + (size_t)row * N + col)       = v0;
            *(float2*)(C + (size_t)(row + 8) * N + col) = v1;
        }
    }
}

// ---------------------------------------------------------------------------
__global__ __launch_bounds__(256) void round_tf32_kernel(
    const float* __restrict__ src, float* __restrict__ dst, int n4)
{
    const int i = blockIdx.x * blockDim.x + threadIdx.x;
    if (i >= n4) return;
    const float4 v = ((const float4*)src)[i];
    uint4 r;
    r.x = f2tf32(v.x); r.y = f2tf32(v.y);
    r.z = f2tf32(v.z); r.w = f2tf32(v.w);
    ((uint4*)dst)[i] = r;
}

// ---------------------------------------------------------------------------
// Attention over heads — register-tiled, alignment-fixed.
// 8 tokens/CTA, 128 threads, 16 threads/token. Thread (I,J): 4x4 score tile,
// softmax via shfl in 4-thread J-groups, out rows 4I+r x d-cols [16J,16J+16).
// RPITCH=68 (float4-aligned; 12*68 = 16 mod 32 -> J-threads spread 16B-groups
// {0,4}); TPITCH=3544 (= 24 mod 32 -> token pair adds {0,6}); worst-case
// 2-way smem conflicts.
// ---------------------------------------------------------------------------
#define TOKPC  8
#define RPITCH 68
#define POFF   3264        // 48 * RPITCH
#define TPITCH 3544        // POFF + 272 (P) + 8 pad; %4==0, %32==24
#define ATTN_SMEM (TOKPC * TPITCH * 4)   // 113408 B

__global__ __launch_bounds__(128) void attn_kernel(
    const float* __restrict__ qkv, float* __restrict__ y)
{
    extern __shared__ float sh[];
    const int tid = threadIdx.x;
    const int tokBlk = blockIdx.x * TOKPC;

    // cooperative load: 8 tokens x 3072 floats, re-laid to 48 rows x pitch 68
    const float4* src = (const float4*)(qkv + (size_t)tokBlk * C3);
    #pragma unroll
    for (int it = 0; it < (TOKPC * 768) / 128; it++) {
        const int i  = it * 128 + tid;
        const int t  = i / 768;
        const int rr = (i % 768) >> 4;
        const int c4 = i & 15;
        *(float4*)(sh + t * TPITCH + rr * RPITCH + c4 * 4) = src[i];
    }
    __syncthreads();

    const int tok = tid >> 4;       // 0..7
    const int j   = tid & 15;
    const int I   = j >> 2;         // h quad
    const int J   = j & 3;          // g quad / d 16-block
    float* tb = sh + tok * TPITCH;

    // ---- scores: S[4I+r][4J+c] = q_{4I+r} . k_{4J+c} ----
    float s[4][4];
    #pragma unroll
    for (int r = 0; r < 4; r++)
        #pragma unroll
        for (int c = 0; c < 4; c++) s[r][c] = 0.0f;

    #pragma unroll
    for (int dd = 0; dd < 16; dd++) {
        float4 qv[4], kv[4];
        #pragma unroll
        for (int r = 0; r < 4; r++)
            qv[r] = *(const float4*)(tb + (12 * I + 3 * r) * RPITCH + dd * 4);
        #pragma unroll
        for (int c = 0; c < 4; c++)
            kv[c] = *(const float4*)(tb + (12 * J + 3 * c + 1) * RPITCH + dd * 4);
        #pragma unroll
        for (int r = 0; r < 4; r++)
            #pragma unroll
            for (int c = 0; c < 4; c++)
                s[r][c] += qv[r].x * kv[c].x + qv[r].y * kv[c].y
                         + qv[r].z * kv[c].z + qv[r].w * kv[c].w;
    }

    // ---- softmax over g (16 cols span 4 J-threads); scale 1/8 folded in ----
    float den[4];
    #pragma unroll
    for (int r = 0; r < 4; r++) {
        float mx = fmaxf(fmaxf(s[r][0], s[r][1]), fmaxf(s[r][2], s[r][3]));
        mx = fmaxf(mx, __shfl_xor_sync(0xFFFFFFFFu, mx, 1));
        mx = fmaxf(mx, __shfl_xor_sync(0xFFFFFFFFu, mx, 2));
        float sum = 0.0f;
        #pragma unroll
        for (int c = 0; c < 4; c++) {
            s[r][c] = __expf((s[r][c] - mx) * 0.125f);
            sum += s[r][c];
        }
        sum += __shfl_xor_sync(0xFFFFFFFFu, sum, 1);
        sum += __shfl_xor_sync(0xFFFFFFFFu, sum, 2);
        den[r] = 1.0f / sum;
    }

    // ---- P (unnormalized exp) to smem ----
    float* P = tb + POFF;
    #pragma unroll
    for (int r = 0; r < 4; r++)
        #pragma unroll
        for (int c = 0; c < 4; c++)
            P[(4 * I + r) * 17 + (4 * J + c)] = s[r][c];
    __syncwarp();

    // ---- out: O[4I+r][16J + cc] = den[r] * sum_g P[4I+r][g] * v[g][16J+cc] ----
    float o[4][16];
    #pragma unroll
    for (int r = 0; r < 4; r++)
        #pragma unroll
        for (int cc = 0; cc < 16; cc++) o[r][cc] = 0.0f;

    #pragma unroll
    for (int g = 0; g < 16; g++) {
        float a[4];
        #pragma unroll
        for (int r = 0; r < 4; r++) a[r] = P[(4 * I + r) * 17 + g];
        const float* vr = tb + (3 * g + 2) * RPITCH + 16 * J;
        float4 v0 = *(const float4*)(vr);
        float4 v1 = *(const float4*)(vr + 4);
        float4 v2 = *(const float4*)(vr + 8);
        float4 v3 = *(const float4*)(vr + 12);
        #pragma unroll
        for (int r = 0; r < 4; r++) {
            o[r][0]  += a[r] * v0.x;  o[r][1]  += a[r] * v0.y;
            o[r][2]  += a[r] * v0.z;  o[r][3]  += a[r] * v0.w;
            o[r][4]  += a[r] * v1.x;  o[r][5]  += a[r] * v1.y;
            o[r][6]  += a[r] * v1.z;  o[r][7]  += a[r] * v1.w;
            o[r][8]  += a[r] * v2.x;  o[r][9]  += a[r] * v2.y;
            o[r][10] += a[r] * v2.z;  o[r][11] += a[r] * v2.w;
            o[r][12] += a[r] * v3.x;  o[r][13] += a[r] * v3.y;
            o[r][14] += a[r] * v3.z;  o[r][15] += a[r] * v3.w;
        }
    }

    // ---- store y (tf32-rounded), rows = own h rows (den matches) ----
    float* yt = y + (size_t)(tokBlk + tok) * CDIM;
    #pragma unroll
    for (int r = 0; r < 4; r++) {
        const int h = 4 * I + r;
        #pragma unroll
        for (int q = 0; q < 4; q++) {
            uint4 w;
            w.x = f2tf32(o[r][q * 4 + 0] * den[r]);
            w.y = f2tf32(o[r][q * 4 + 1] * den[r]);
            w.z = f2tf32(o[r][q * 4 + 2] * den[r]);
            w.w = f2tf32(o[r][q * 4 + 3] * den[r]);
            *(uint4*)(yt + h * 64 + 16 * J + q * 4) = w;
        }
    }
}

// ---------------------------------------------------------------------------
extern "C" void kernel_launch(void* const* d_in, const int* in_sizes, int n_in,
                              void* d_out, int out_size)
{
    const float* x    = (const float*)d_in[0];
    const float* Wqkv = (const float*)d_in[1];
    const float* Wout = (const float*)d_in[2];
    const float* bout = (const float*)d_in[3];
    float* out = (float*)d_out;

    float *qkv, *y, *xt, *w1t, *w2t;
    cudaGetSymbolAddress((void**)&qkv, g_qkv);
    cudaGetSymbolAddress((void**)&y,   g_y);
    cudaGetSymbolAddress((void**)&xt,  g_xt);
    cudaGetSymbolAddress((void**)&w1t, g_w1t);
    cudaGetSymbolAddress((void**)&w2t, g_w2t);

    cudaFuncSetAttribute(tf32_gemm, cudaFuncAttributeMaxDynamicSharedMemorySize, SMEM_B);
    cudaFuncSetAttribute(attn_kernel, cudaFuncAttributeMaxDynamicSharedMemorySize, ATTN_SMEM);

    // tf32 rounding passes (rna)
    round_tf32_kernel<<<(NTOK * CDIM / 4 + 255) / 256, 256>>>(x, xt, NTOK * CDIM / 4);
    round_tf32_kernel<<<(C3 * CDIM / 4 + 255) / 256, 256>>>(Wqkv, w1t, C3 * CDIM / 4);
    round_tf32_kernel<<<(CDIM * CDIM / 4 + 255) / 256, 256>>>(Wout, w2t, CDIM * CDIM / 4);

    // GEMM1: qkv = xt @ w1t^T   (16384 x 3072, K=1024)
    tf32_gemm<<<dim3(C3 / 128, NTOK / 128), 256, SMEM_B>>>(
        xt, w1t, nullptr, qkv, NTOK, C3, CDIM);

    // attention over heads (emits tf32-rounded y)
    attn_kernel<<<NTOK / TOKPC, 128, ATTN_SMEM>>>(qkv, y);

    // GEMM2: out = y @ w2t^T + bout   (16384 x 1024, K=1024)
    tf32_gemm<<<dim3(CDIM / 128, NTOK / 128), 256, SMEM_B>>>(
        y, w2t, bout, out, NTOK, CDIM, CDIM);
}